// round 6
// baseline (speedup 1.0000x reference)
#include <cuda_runtime.h>
#include <math.h>

#define G    512
#define NPG  90
#define NTOT (G*NPG)      // 46080
#define FIN  90
#define HC   64
#define KP   70
#define POOLW (KP*HC)     // 4480

// ---------------- scratch (device globals; no allocation allowed) ----------
// NOTE: these symbols are referenced ONLY inside device code. Passing their
// address from host code yields the host shadow object's address, which on
// GB300 (ATS, pageableMemoryAccess=1) silently reads host BSS zeros.
__device__ float g_A[G*NPG*NPG];     // normalized adjacency (row = dst), 16.6MB
__device__ float g_PQ[NTOT*128];     // [x@W1l | x@W1r]
__device__ float g_H1[NTOT*HC];      // conv1 output (x_train)
__device__ float g_RW[NTOT*128];     // [relu(h1)@W2l | relu(h1)@W2r]
__device__ float g_H2[NTOT*HC];      // conv2 output
__device__ float g_pool[G*POOLW];    // sort-pooled features
__device__ int   g_mode;             // 1 = edge data is int64 (odd words zero)

// ---------------- edge dtype detection -------------------------------------
__global__ void detect_kernel(const int* __restrict__ ei) {
    if (threadIdx.x == 0 && blockIdx.x == 0) {
        int allzero = 1;
        for (int i = 0; i < 512; i++)
            if (ei[2*i + 1] != 0) { allzero = 0; break; }
        g_mode = allzero;
    }
}

// ---------------- adjacency build ------------------------------------------
__global__ void zeroA_kernel() {
    int n = G*NPG*NPG;
    for (int i = blockIdx.x*blockDim.x + threadIdx.x; i < n; i += gridDim.x*blockDim.x)
        g_A[i] = 0.f;
}

__global__ void edge_kernel(const int* __restrict__ ei, int E) {
    int e = blockIdx.x*blockDim.x + threadIdx.x;
    if (e >= E) return;
    int s, d;
    if (g_mode) { s = ei[2*e]; d = ei[2*(E + e)]; }   // int64 storage
    else        { s = ei[e];   d = ei[E + e];      }  // int32 storage
    if ((unsigned)s >= NTOT || (unsigned)d >= NTOT) return;
    int g  = d / NPG;
    int sl = s - g*NPG;
    int dl = d - g*NPG;
    if ((unsigned)sl >= NPG) return;
    atomicAdd(&g_A[(size_t)(g*NPG + dl)*NPG + sl], 1.0f);
}

// one warp per adjacency row: rowsum -> scale by 1/max(sum,1)
__global__ void norm_kernel() {
    int warp = (blockIdx.x*blockDim.x + threadIdx.x) >> 5;
    int lane = threadIdx.x & 31;
    if (warp >= NTOT) return;
    float* row = &g_A[(size_t)warp*NPG];
    float s = 0.f;
    for (int j = lane; j < NPG; j += 32) s += row[j];
    #pragma unroll
    for (int o = 16; o; o >>= 1) s += __shfl_xor_sync(0xffffffffu, s, o);
    float inv = 1.0f / fmaxf(s, 1.0f);
    for (int j = lane; j < NPG; j += 32) row[j] *= inv;
}

// ---------------- node GEMM: X[N,KD] @ [Wl|Wr] -> sel{g_PQ,g_RW}[N,128] -----
// INSEL: 0 = external pointer X (conv1), 1 = internal g_H1 (conv2)
template<int KD, bool RELU, int INSEL, int OUTSEL>
__global__ __launch_bounds__(256) void gemm_node(const float* __restrict__ Xext,
                                                 const float* __restrict__ Wl,
                                                 const float* __restrict__ Wr) {
    __shared__ float ws[32*128];
    __shared__ float xs[32*KD];
    const float* X = INSEL ? (const float*)g_H1 : Xext;
    float* out = OUTSEL ? g_RW : g_PQ;
    int t = threadIdx.x;
    int r0blk = blockIdx.x * 32;

    for (int idx = t; idx < 32*KD; idx += 256) {
        int r = idx / KD, k = idx - r*KD;
        float v = X[(size_t)(r0blk + r)*KD + k];
        if (RELU) v = fmaxf(v, 0.f);
        xs[idx] = v;
    }

    int tx = t & 31, ty = t >> 5;
    int c0 = tx*4, r0 = ty*4;
    float acc[4][4];
    #pragma unroll
    for (int i = 0; i < 4; i++)
        #pragma unroll
        for (int j = 0; j < 4; j++) acc[i][j] = 0.f;

    for (int kt = 0; kt < KD; kt += 32) {
        int kc = (KD - kt < 32) ? (KD - kt) : 32;
        __syncthreads();                       // also covers xs on first pass
        for (int idx = t; idx < kc*128; idx += 256) {
            int k = idx >> 7, c = idx & 127;
            ws[idx] = (c < 64) ? Wl[(kt + k)*64 + c] : Wr[(kt + k)*64 + (c - 64)];
        }
        __syncthreads();
        for (int k = 0; k < kc; k++) {
            float4 b = *(const float4*)&ws[k*128 + c0];
            float a0 = xs[(r0+0)*KD + kt + k];
            float a1 = xs[(r0+1)*KD + kt + k];
            float a2 = xs[(r0+2)*KD + kt + k];
            float a3 = xs[(r0+3)*KD + kt + k];
            acc[0][0]+=a0*b.x; acc[0][1]+=a0*b.y; acc[0][2]+=a0*b.z; acc[0][3]+=a0*b.w;
            acc[1][0]+=a1*b.x; acc[1][1]+=a1*b.y; acc[1][2]+=a1*b.z; acc[1][3]+=a1*b.w;
            acc[2][0]+=a2*b.x; acc[2][1]+=a2*b.y; acc[2][2]+=a2*b.z; acc[2][3]+=a2*b.w;
            acc[3][0]+=a3*b.x; acc[3][1]+=a3*b.y; acc[3][2]+=a3*b.z; acc[3][3]+=a3*b.w;
        }
    }
    #pragma unroll
    for (int i = 0; i < 4; i++) {
        float4 v = make_float4(acc[i][0], acc[i][1], acc[i][2], acc[i][3]);
        *(float4*)&out[(size_t)(r0blk + r0 + i)*128 + c0] = v;
    }
}

// ---------------- per-graph aggregation: out = A_g @ P_g + skip + bias ------
template<int INSEL, int OUTSEL>   // INSEL: 0=g_PQ 1=g_RW ; OUTSEL: 0=g_H1 1=g_H2
__global__ __launch_bounds__(256) void aggr_kernel(const float* __restrict__ bias) {
    __shared__ float As[NPG*NPG];
    const float* PQ = INSEL ? g_RW : g_PQ;
    float* out = OUTSEL ? g_H2 : g_H1;
    int g = blockIdx.x;
    int t = threadIdx.x;

    for (int idx = t; idx < NPG*NPG; idx += 256) As[idx] = g_A[(size_t)g*NPG*NPG + idx];
    __syncthreads();

    int c = t & 63, rg = t >> 6;      // 4 row-groups: rows rg, rg+4, ...
    float acc[23];
    #pragma unroll
    for (int i = 0; i < 23; i++) acc[i] = 0.f;

    const float* Pg = PQ + (size_t)g*NPG*128;
    for (int j = 0; j < NPG; j++) {
        float w = __ldg(&Pg[j*128 + c]);
        #pragma unroll
        for (int i = 0; i < 23; i++) {
            int row = rg + 4*i;
            if (row < NPG) acc[i] += As[row*NPG + j] * w;
        }
    }
    float bc = bias[c];
    #pragma unroll
    for (int i = 0; i < 23; i++) {
        int row = rg + 4*i;
        if (row < NPG) {
            int n = g*NPG + row;
            out[(size_t)n*HC + c] = acc[i] + Pg[row*128 + 64 + c] + bc;
        }
    }
}

// ---------------- copy h1 (x_train) into d_out tail -------------------------
__global__ void copy_h1_kernel(float* __restrict__ dst) {
    int n = NTOT*HC/4;
    const float4* s = (const float4*)g_H1;
    float4* d = (float4*)dst;
    for (int i = blockIdx.x*blockDim.x + threadIdx.x; i < n; i += gridDim.x*blockDim.x)
        d[i] = s[i];
}

// ---------------- sort-pool: top-70 by channel 63, stable desc --------------
__global__ void sortpool_kernel() {
    __shared__ float key[NPG];
    __shared__ int   slot[KP];
    int g = blockIdx.x, t = threadIdx.x;
    if (t < NPG) key[t] = g_H2[(size_t)(g*NPG + t)*HC + 63];
    __syncthreads();
    if (t < NPG) {
        float v = key[t];
        int rank = 0;
        for (int j = 0; j < NPG; j++) {
            float u = key[j];
            rank += (u > v) || (u == v && j < t);
        }
        if (rank < KP) slot[rank] = t;
    }
    __syncthreads();
    for (int idx = t; idx < POOLW; idx += 128) {
        int r = idx >> 6, c = idx & 63;
        g_pool[(size_t)g*POOLW + idx] = g_H2[(size_t)(g*NPG + slot[r])*HC + c];
    }
}

// ---------------- final: pool @ Wl1 + bl1, @ Wl2 + bl2, sigmoid -------------
__global__ __launch_bounds__(256) void final_kernel(const float* __restrict__ Wl1,
                                                    const float* __restrict__ bl1,
                                                    const float* __restrict__ Wl2,
                                                    const float* __restrict__ bl2,
                                                    float* __restrict__ outG) {
    __shared__ float ws[64*64];
    __shared__ float ps[8*64];
    __shared__ float pbuf[8*64];
    int t = threadIdx.x;
    int g0 = blockIdx.x * 8;
    int c = t & 63, gi = t >> 6;       // gi in 0..3, handles graphs gi and gi+4
    float acc0 = 0.f, acc1 = 0.f;

    for (int chunk = 0; chunk < POOLW/64; chunk++) {
        int m0 = chunk*64;
        __syncthreads();
        for (int idx = t; idx < 64*64; idx += 256)
            ws[idx] = Wl1[(size_t)(m0 + (idx >> 6))*64 + (idx & 63)];
        for (int idx = t; idx < 8*64; idx += 256) {
            int gg = idx >> 6, mm = idx & 63;
            ps[idx] = g_pool[(size_t)(g0 + gg)*POOLW + m0 + mm];
        }
        __syncthreads();
        #pragma unroll
        for (int kk = 0; kk < 64; kk++) {
            float w = ws[kk*64 + c];
            acc0 += ps[gi*64 + kk] * w;
            acc1 += ps[(gi+4)*64 + kk] * w;
        }
    }
    __syncthreads();
    pbuf[gi*64 + c]     = acc0 + bl1[c];
    pbuf[(gi+4)*64 + c] = acc1 + bl1[c];
    __syncthreads();
    int w = t >> 5, lane = t & 31;     // 8 warps -> 8 graphs
    float v = pbuf[w*64 + lane]*Wl2[lane] + pbuf[w*64 + lane + 32]*Wl2[lane + 32];
    #pragma unroll
    for (int o = 16; o; o >>= 1) v += __shfl_xor_sync(0xffffffffu, v, o);
    if (lane == 0) outG[g0 + w] = 1.f / (1.f + expf(-(v + bl2[0])));
}

// ---------------------------------------------------------------------------
// kernel_launch: identify inputs by SIZE SIGNATURE (robust to metadata order),
// then kernel launches only. NO device-symbol addresses cross host/device.
extern "C" void kernel_launch(void* const* d_in, const int* in_sizes, int n_in,
                              void* d_out, int out_size) {
    const float *x = 0, *W1l = 0, *W1r = 0, *W2l = 0, *W2r = 0;
    const float *Wl1 = 0, *bl2 = 0;
    const int   *ei = 0;
    int i5760 = 0, i4096 = 0;
    int idx64[8]; int n64 = 0;

    for (int i = 0; i < n_in; i++) {
        int sz = in_sizes[i];
        const float* p = (const float*)d_in[i];
        switch (sz) {
            case 4147200: x   = p; break;                       // [46080,90]
            case 1843200: ei  = (const int*)d_in[i]; break;     // [2,921600]
            case  286720: Wl1 = p; break;                       // [4480,64]
            case    5760: if (i5760++ == 0) W1l = p; else W1r = p; break;
            case    4096: if (i4096++ == 0) W2l = p; else W2r = p; break;
            case      64: if (n64 < 8) idx64[n64++] = i; break; // b1,b2,bl1,Wl2
            case       1: bl2 = p; break;
            default: break;                                     // batch unused
        }
    }
    // Disambiguate the four 64-element inputs by global ordering mode:
    // case-sensitive alphabetical starts with W1l (5760) and puts Wl2 first
    // in the 64-group; dict / signature order puts Wl2 last.
    const float *b1, *b2, *bl1, *Wl2;
    if (n_in > 0 && in_sizes[0] == 5760) {          // alphabetical (W* first)
        Wl2 = (const float*)d_in[idx64[0]];
        b1  = (const float*)d_in[idx64[1]];
        b2  = (const float*)d_in[idx64[2]];
        bl1 = (const float*)d_in[idx64[3]];
    } else {                                        // dict / signature order
        b1  = (const float*)d_in[idx64[0]];
        b2  = (const float*)d_in[idx64[1]];
        bl1 = (const float*)d_in[idx64[2]];
        Wl2 = (const float*)d_in[idx64[3]];
    }

    float* outG = (float*)d_out;            // [512] sigmoid outputs
    int E = 1843200 / 2;

    // 1. adjacency (with device-side edge dtype detection)
    detect_kernel<<<1, 32>>>(ei);
    zeroA_kernel<<<4050, 1024>>>();
    edge_kernel<<<(E + 255)/256, 256>>>(ei, E);
    norm_kernel<<<NTOT/8, 256>>>();

    // 2. conv1: projections -> g_PQ, aggregation -> g_H1 (x_train)
    gemm_node<90, false, 0, 0><<<NTOT/32, 256>>>(x, W1l, W1r);
    aggr_kernel<0, 0><<<G, 256>>>(b1);

    // 3. conv2: input g_H1 selected INSIDE the kernel (relu on load) -> g_RW
    gemm_node<64, true, 1, 1><<<NTOT/32, 256>>>(nullptr, W2l, W2r);
    aggr_kernel<1, 1><<<G, 256>>>(b2);

    // 4. sort-pool + MLP head
    sortpool_kernel<<<G, 128>>>();
    final_kernel<<<G/8, 256>>>(Wl1, bl1, Wl2, bl2, outG);

    // 5. x_train into d_out tail ONLY if the harness allocated room for it
    if (out_size >= G + NTOT*HC)
        copy_h1_kernel<<<1024, 256>>>((float*)d_out + G);
}